// round 7
// baseline (speedup 1.0000x reference)
#include <cuda_runtime.h>
#include <cuda_fp16.h>
#include <cstdint>

#define H 512
#define W 512
#define HW (H*W)
#define NB 2
#define NC 21
#define NPIX (NB*HW)
#define NTAP 25

// ping-pong q buffers (fp32) + combined coefficient field (fp16)
__device__ float  g_qA[NB*NC*HW];
__device__ float  g_qB[NB*NC*HW];
__device__ __half g_wch[NTAP*NB*HW];   // SoA: [tap][b][y][x]

__device__ __forceinline__ int reflect_idx(int i, int n) {
    if (i < 0) i = -i;
    if (i >= n) i = 2*n - 2 - i;
    return i;
}

// packed fp32x2 helpers (FFMA2 — PTX-only pattern on sm_103a)
__device__ __forceinline__ unsigned long long pk2(float lo, float hi) {
    unsigned long long r;
    asm("mov.b64 %0, {%1, %2};" : "=l"(r) : "f"(lo), "f"(hi));
    return r;
}
__device__ __forceinline__ void upk2(float& lo, float& hi, unsigned long long v) {
    asm("mov.b64 {%0, %1}, %2;" : "=f"(lo), "=f"(hi) : "l"(v));
}
#define FMA2(acc, a, b) \
    asm("fma.rn.f32x2 %0, %1, %2, %0;" : "+l"(acc) : "l"(a), "l"(b))

// ---------------------------------------------------------------------------
// Kernel 1: q0 = softmax(unary)
// ---------------------------------------------------------------------------
__global__ void __launch_bounds__(256) init_softmax(const float* __restrict__ unary,
                                                    float* __restrict__ q) {
    int idx = blockIdx.x * 256 + threadIdx.x;
    if (idx >= NPIX) return;
    int b = idx / HW, pix = idx % HW;
    const float* u = unary + (size_t)b * NC * HW + pix;
    float e[NC];
    float s = 0.f;
#pragma unroll
    for (int c = 0; c < NC; c++) { e[c] = __expf(u[c*HW]); s += e[c]; }
    float inv = 1.f / s;
    float* qo = q + (size_t)b * NC * HW + pix;
#pragma unroll
    for (int c = 0; c < NC; c++) qo[c*HW] = e[c] * inv;
}

// ---------------------------------------------------------------------------
// Kernel 2: combined coefficients (fp16 output)
//   Wc[t] = g2d[t] + w_rgb[t]/sum(w_rgb) + w_edge[t]/sum(w_edge)
// ---------------------------------------------------------------------------
__global__ void __launch_bounds__(256) compute_weights(const float* __restrict__ image,
                                                       const float* __restrict__ edges) {
    __shared__ float sg[4][12][36];   // rgb + edge, tile 32x8 + halo 2
    int tx = threadIdx.x, ty = threadIdx.y;
    int b = blockIdx.z;
    int x0 = blockIdx.x * 32, y0 = blockIdx.y * 8;
    int tid = ty * 32 + tx;

    for (int idx = tid; idx < 4*12*36; idx += 256) {
        int ch = idx / (12*36);
        int r  = idx % (12*36);
        int ry = r / 36, sx = r % 36;
        int gy = reflect_idx(y0 + ry - 2, H);
        int gx = reflect_idx(x0 + sx - 2, W);
        float v;
        if (ch < 3) v = image[((size_t)(b*3 + ch))*HW + gy*W + gx];
        else        v = edges[(size_t)b*HW + gy*W + gx];
        sg[ch][ry][sx] = v;
    }
    __syncthreads();

    float sp[5], g2[5];
    {
        float s = 0.f;
#pragma unroll
        for (int i = 0; i < 5; i++) {
            float x = (float)(i - 2);
            sp[i] = __expf(-x*x * 0.02f);    // spatial, sigma_space=5 (norm cancels)
            float g = __expf(-2.f * x*x);    // blur kernel, sigma=0.5
            g2[i] = g; s += g;
        }
        float inv = 1.f / s;
#pragma unroll
        for (int i = 0; i < 5; i++) g2[i] *= inv;
    }

    int ry = ty + 2, rx = tx + 2;
    float cr = sg[0][ry][rx], cg = sg[1][ry][rx], cb = sg[2][ry][rx], ce = sg[3][ry][rx];

    float wr[NTAP], we[NTAP];
    float sr = 0.f, se = 0.f;
#pragma unroll
    for (int dy = 0; dy < 5; dy++) {
#pragma unroll
        for (int dx = 0; dx < 5; dx++) {
            int t = dy*5 + dx;
            float d = fabsf(sg[0][ry+dy-2][rx+dx-2] - cr)
                    + fabsf(sg[1][ry+dy-2][rx+dx-2] - cg)
                    + fabsf(sg[2][ry+dy-2][rx+dx-2] - cb);
            float s2 = sp[dy] * sp[dx];
            float w  = s2 * __expf(-2.f * d * d);
            wr[t] = w; sr += w;
            float de = fabsf(sg[3][ry+dy-2][rx+dx-2] - ce);
            float w2 = s2 * __expf(-2.f * de * de);
            we[t] = w2; se += w2;
        }
    }
    float isr = 1.f / sr, ise = 1.f / se;
    int pix = b*HW + (y0 + ty)*W + (x0 + tx);
#pragma unroll
    for (int dy = 0; dy < 5; dy++) {
#pragma unroll
        for (int dx = 0; dx < 5; dx++) {
            int t = dy*5 + dx;
            g_wch[t*(NB*HW) + pix] = __float2half(g2[dy]*g2[dx] + wr[t]*isr + we[t]*ise);
        }
    }
}

// ---------------------------------------------------------------------------
// Kernel 3: one CRF iteration.
// Tile 64x8, block (32,8)=256 thr, 2 px/thread, 2 CTAs/SM.
// q fp32; fill via cp.async.cg 16B; coef fp16 + L2 prefetch; packed FFMA2.
// smem window [NC][SH][SW=72] floats, starting at x0-4.
// ---------------------------------------------------------------------------
#define TX 64
#define TY 8
#define SW 72            // x0-4 .. x0+67
#define SH 12            // TY + 4
#define ROWB (SW*4)      // 288 bytes per smem row
#define NCHUNK (NC*SH*18)   // 16B float4 chunks: 4536

__global__ void __launch_bounds__(256, 2) crf_iter(const float* __restrict__ unary,
                                                   const float* __restrict__ qin,
                                                   float* __restrict__ qout) {
    __shared__ float sq[NC*SH*SW];
    int tx = threadIdx.x, ty = threadIdx.y;
    int b = blockIdx.z;
    int x0 = blockIdx.x * TX, y0 = blockIdx.y * TY;
    int tid = ty * 32 + tx;

    const float* qb = qin + (size_t)b * NC * HW;
    uint32_t sbase = (uint32_t)__cvta_generic_to_shared(sq);

    bool xInt = (blockIdx.x != 0) && (blockIdx.x != (int)gridDim.x - 1);

    int xl  = tx * 2;
    int gx0 = x0 + xl;
    int gy  = y0 + ty;
    int wbase = b*HW + gy*W + gx0;
    const __half* wp0 = g_wch + wbase;
    const float*  ub  = unary + (size_t)b * NC * HW + gy*W + gx0;

    if (xInt) {
        // fire-and-forget smem fill first
#pragma unroll
        for (int it = 0; it < 18; it++) {
            int idx = tid + it*256;
            if (idx < NCHUNK) {
                int cx  = idx % 18;
                int row = idx / 18;
                int ry  = row % SH;
                int c   = row / SH;
                int gyv = reflect_idx(y0 + ry - 2, H);
                const float* src = qb + c*HW + gyv*W + (x0 - 4 + cx*4);
                uint32_t dst = sbase + (uint32_t)(row*ROWB + cx*16);
                asm volatile("cp.async.cg.shared.global [%0], [%1], 16;"
                             :: "r"(dst), "l"(src));
            }
        }
        asm volatile("cp.async.commit_group;");
        // L2 prefetch of coef + unary while the fill drains
#pragma unroll
        for (int t = 0; t < NTAP; t++)
            asm volatile("prefetch.global.L2 [%0];" :: "l"(wp0 + (size_t)t*(NB*HW)));
#pragma unroll
        for (int c = 0; c < NC; c++)
            asm volatile("prefetch.global.L2 [%0];" :: "l"(ub + (size_t)c*HW));
        asm volatile("cp.async.wait_group 0;" ::: "memory");
    } else {
#pragma unroll
        for (int t = 0; t < NTAP; t++)
            asm volatile("prefetch.global.L2 [%0];" :: "l"(wp0 + (size_t)t*(NB*HW)));
#pragma unroll
        for (int c = 0; c < NC; c++)
            asm volatile("prefetch.global.L2 [%0];" :: "l"(ub + (size_t)c*HW));
#pragma unroll 3
        for (int it = 0; it < 18; it++) {
            int idx = tid + it*256;
            if (idx < NCHUNK) {
                int cx  = idx % 18;
                int row = idx / 18;
                int ry  = row % SH;
                int c   = row / SH;
                int gyv = reflect_idx(y0 + ry - 2, H);
                const float* src = qb + c*HW + gyv*W;
                float4 v;
                v.x = src[reflect_idx(x0 - 4 + cx*4,     W)];
                v.y = src[reflect_idx(x0 - 4 + cx*4 + 1, W)];
                v.z = src[reflect_idx(x0 - 4 + cx*4 + 2, W)];
                v.w = src[reflect_idx(x0 - 4 + cx*4 + 3, W)];
                *reinterpret_cast<float4*>(
                    reinterpret_cast<char*>(sq) + row*ROWB + cx*16) = v;
            }
        }
    }
    __syncthreads();

    unsigned long long acc[NC];
#pragma unroll
    for (int cc = 0; cc < NC; cc++) acc[cc] = 0ULL;

#pragma unroll
    for (int dy = 0; dy < 5; dy++) {
        // packed coef pairs (fp16 -> fp32x2): (w[t,gx0], w[t,gx0+1])
        unsigned long long C0, C1, C2, C3, C4;
        {
            const __half* wp = wp0 + (size_t)(dy*5)*(NB*HW);
            float2 f;
            f = __half22float2(*reinterpret_cast<const __half2*>(wp));
            C0 = pk2(f.x, f.y);
            f = __half22float2(*reinterpret_cast<const __half2*>(wp + NB*HW));
            C1 = pk2(f.x, f.y);
            f = __half22float2(*reinterpret_cast<const __half2*>(wp + 2*(size_t)NB*HW));
            C2 = pk2(f.x, f.y);
            f = __half22float2(*reinterpret_cast<const __half2*>(wp + 3*(size_t)NB*HW));
            C3 = pk2(f.x, f.y);
            f = __half22float2(*reinterpret_cast<const __half2*>(wp + 4*(size_t)NB*HW));
            C4 = pk2(f.x, f.y);
        }
        // window q[gx0-2 .. gx0+3] = smem floats [xl+2 .. xl+7] of row (ty+dy)
        const float* rowb = sq + (ty + dy)*SW + xl + 2;
#pragma unroll
        for (int ch = 0; ch < NC; ch++) {
            const float* rp = rowb + ch*(SH*SW);
            float2 a0 = *reinterpret_cast<const float2*>(rp);      // (v0,v1)
            float2 a1 = *reinterpret_cast<const float2*>(rp + 2);  // (v2,v3)
            float2 a2 = *reinterpret_cast<const float2*>(rp + 4);  // (v4,v5)
            unsigned long long A0 = pk2(a0.x, a0.y);
            unsigned long long B0 = pk2(a0.y, a1.x);
            unsigned long long A1 = pk2(a1.x, a1.y);
            unsigned long long B1 = pk2(a1.y, a2.x);
            unsigned long long A2 = pk2(a2.x, a2.y);
            FMA2(acc[ch], C0, A0);
            FMA2(acc[ch], C1, B0);
            FMA2(acc[ch], C2, A1);
            FMA2(acc[ch], C3, B1);
            FMA2(acc[ch], C4, A2);
        }
    }

    // q_out = softmax(unary - F)   (softmax shift-invariance kills _compat colsum)
    float e0[NC], e1[NC];
    float s0 = 0.f, s1 = 0.f;
#pragma unroll
    for (int ch = 0; ch < NC; ch++) {
        float2 u = *reinterpret_cast<const float2*>(ub + (size_t)ch*HW);
        float f0, f1;
        upk2(f0, f1, acc[ch]);
        e0[ch] = __expf(u.x - f0);
        e1[ch] = __expf(u.y - f1);
        s0 += e0[ch]; s1 += e1[ch];
    }
    float i0 = 1.f / s0, i1 = 1.f / s1;
    float* qo = qout + (size_t)b * NC * HW + gy*W + gx0;
#pragma unroll
    for (int ch = 0; ch < NC; ch++) {
        float2 o; o.x = e0[ch]*i0; o.y = e1[ch]*i1;
        *reinterpret_cast<float2*>(qo + ch*HW) = o;
    }
}

// ---------------------------------------------------------------------------
extern "C" void kernel_launch(void* const* d_in, const int* in_sizes, int n_in,
                              void* d_out, int out_size) {
    const float *unary = nullptr, *image = nullptr, *edges = nullptr;
    for (int i = 0; i < n_in; i++) {
        if      (in_sizes[i] == NB*NC*HW) unary = (const float*)d_in[i];
        else if (in_sizes[i] == NB*3*HW)  image = (const float*)d_in[i];
        else if (in_sizes[i] == NB*HW)    edges = (const float*)d_in[i];
    }
    float* out = (float*)d_out;

    float *qA = nullptr, *qB = nullptr;
    cudaGetSymbolAddress((void**)&qA, g_qA);
    cudaGetSymbolAddress((void**)&qB, g_qB);

    init_softmax<<<(NPIX + 255)/256, 256>>>(unary, qA);
    compute_weights<<<dim3(W/32, H/8, NB), dim3(32, 8)>>>(image, edges);

    dim3 gi(W/TX, H/TY, NB), bi(32, 8);
    const float* cur = qA;
    for (int it = 0; it < 10; it++) {
        float* dst = (it == 9) ? out : ((cur == qA) ? qB : qA);
        crf_iter<<<gi, bi>>>(unary, cur, dst);
        cur = dst;
    }
}

// round 8
// speedup vs baseline: 1.4335x; 1.4335x over previous
#include <cuda_runtime.h>
#include <cstdint>

#define H 512
#define W 512
#define HW (H*W)
#define NB 2
#define NC 21
#define NPIX (NB*HW)
#define NTAP 25

// ping-pong q buffers + combined coefficient field, all fp32
__device__ float g_qA[NB*NC*HW];
__device__ float g_qB[NB*NC*HW];
__device__ float g_wc[NTAP*NB*HW];   // SoA: [tap][b][y][x]

__device__ __forceinline__ int reflect_idx(int i, int n) {
    if (i < 0) i = -i;
    if (i >= n) i = 2*n - 2 - i;
    return i;
}

// packed fp32x2 helpers (FFMA2 — PTX-only pattern on sm_103a)
__device__ __forceinline__ unsigned long long pk2(float lo, float hi) {
    unsigned long long r;
    asm("mov.b64 %0, {%1, %2};" : "=l"(r) : "f"(lo), "f"(hi));
    return r;
}
__device__ __forceinline__ void upk2(float& lo, float& hi, unsigned long long v) {
    asm("mov.b64 {%0, %1}, %2;" : "=f"(lo), "=f"(hi) : "l"(v));
}
#define FMA2(acc, a, b) \
    asm("fma.rn.f32x2 %0, %1, %2, %0;" : "+l"(acc) : "l"(a), "l"(b))

// ---------------------------------------------------------------------------
// Kernel 1: q0 = softmax(unary)
// ---------------------------------------------------------------------------
__global__ void __launch_bounds__(256) init_softmax(const float* __restrict__ unary,
                                                    float* __restrict__ q) {
    int idx = blockIdx.x * 256 + threadIdx.x;
    if (idx >= NPIX) return;
    int b = idx / HW, pix = idx % HW;
    const float* u = unary + (size_t)b * NC * HW + pix;
    float e[NC];
    float s = 0.f;
#pragma unroll
    for (int c = 0; c < NC; c++) { e[c] = __expf(u[c*HW]); s += e[c]; }
    float inv = 1.f / s;
    float* qo = q + (size_t)b * NC * HW + pix;
#pragma unroll
    for (int c = 0; c < NC; c++) qo[c*HW] = e[c] * inv;
}

// ---------------------------------------------------------------------------
// Kernel 2: combined coefficients (fp32)
//   Wc[t] = g2d[t] + w_rgb[t]/sum(w_rgb) + w_edge[t]/sum(w_edge)
// ---------------------------------------------------------------------------
__global__ void __launch_bounds__(256) compute_weights(const float* __restrict__ image,
                                                       const float* __restrict__ edges) {
    __shared__ float sg[4][12][36];   // rgb + edge, tile 32x8 + halo 2
    int tx = threadIdx.x, ty = threadIdx.y;
    int b = blockIdx.z;
    int x0 = blockIdx.x * 32, y0 = blockIdx.y * 8;
    int tid = ty * 32 + tx;

    for (int idx = tid; idx < 4*12*36; idx += 256) {
        int ch = idx / (12*36);
        int r  = idx % (12*36);
        int ry = r / 36, sx = r % 36;
        int gy = reflect_idx(y0 + ry - 2, H);
        int gx = reflect_idx(x0 + sx - 2, W);
        float v;
        if (ch < 3) v = image[((size_t)(b*3 + ch))*HW + gy*W + gx];
        else        v = edges[(size_t)b*HW + gy*W + gx];
        sg[ch][ry][sx] = v;
    }
    __syncthreads();

    float sp[5], g2[5];
    {
        float s = 0.f;
#pragma unroll
        for (int i = 0; i < 5; i++) {
            float x = (float)(i - 2);
            sp[i] = __expf(-x*x * 0.02f);    // spatial, sigma_space=5 (norm cancels)
            float g = __expf(-2.f * x*x);    // blur kernel, sigma=0.5
            g2[i] = g; s += g;
        }
        float inv = 1.f / s;
#pragma unroll
        for (int i = 0; i < 5; i++) g2[i] *= inv;
    }

    int ry = ty + 2, rx = tx + 2;
    float cr = sg[0][ry][rx], cg = sg[1][ry][rx], cb = sg[2][ry][rx], ce = sg[3][ry][rx];

    float wr[NTAP], we[NTAP];
    float sr = 0.f, se = 0.f;
#pragma unroll
    for (int dy = 0; dy < 5; dy++) {
#pragma unroll
        for (int dx = 0; dx < 5; dx++) {
            int t = dy*5 + dx;
            float d = fabsf(sg[0][ry+dy-2][rx+dx-2] - cr)
                    + fabsf(sg[1][ry+dy-2][rx+dx-2] - cg)
                    + fabsf(sg[2][ry+dy-2][rx+dx-2] - cb);
            float s2 = sp[dy] * sp[dx];
            float w  = s2 * __expf(-2.f * d * d);
            wr[t] = w; sr += w;
            float de = fabsf(sg[3][ry+dy-2][rx+dx-2] - ce);
            float w2 = s2 * __expf(-2.f * de * de);
            we[t] = w2; se += w2;
        }
    }
    float isr = 1.f / sr, ise = 1.f / se;
    int pix = b*HW + (y0 + ty)*W + (x0 + tx);
#pragma unroll
    for (int dy = 0; dy < 5; dy++) {
#pragma unroll
        for (int dx = 0; dx < 5; dx++) {
            int t = dy*5 + dx;
            g_wc[t*(NB*HW) + pix] = g2[dy]*g2[dx] + wr[t]*isr + we[t]*ise;
        }
    }
}

// ---------------------------------------------------------------------------
// Kernel 3: one CRF iteration.
// Tile 64x8, block (32,8)=256 thr, 2 px/thread, 3 CTAs/SM (regs<=85).
// q fp32 everywhere; fill via cp.async.cg 16B; stencil uses packed FFMA2.
// smem window [NC][SH][SW=72] floats, starting at x0-4 (16B-aligned rows).
// ---------------------------------------------------------------------------
#define TX 64
#define TY 8
#define SW 72            // x0-4 .. x0+67
#define SH 12            // TY + 4
#define ROWB (SW*4)      // 288 bytes per smem row (multiple of 16)
#define NCHUNK (NC*SH*18)   // 16B float4 chunks: 4536

__global__ void __launch_bounds__(256, 3) crf_iter(const float* __restrict__ unary,
                                                   const float* __restrict__ qin,
                                                   float* __restrict__ qout) {
    __shared__ float sq[NC*SH*SW];
    int tx = threadIdx.x, ty = threadIdx.y;
    int b = blockIdx.z;
    int x0 = blockIdx.x * TX, y0 = blockIdx.y * TY;
    int tid = ty * 32 + tx;

    const float* qb = qin + (size_t)b * NC * HW;
    uint32_t sbase = (uint32_t)__cvta_generic_to_shared(sq);

    bool xInt = (blockIdx.x != 0) && (blockIdx.x != (int)gridDim.x - 1);

    if (xInt) {
#pragma unroll
        for (int it = 0; it < 18; it++) {
            int idx = tid + it*256;
            if (idx < NCHUNK) {
                int cx  = idx % 18;
                int row = idx / 18;
                int ry  = row % SH;
                int c   = row / SH;
                int gy  = reflect_idx(y0 + ry - 2, H);
                const float* src = qb + c*HW + gy*W + (x0 - 4 + cx*4);
                uint32_t dst = sbase + (uint32_t)(row*ROWB + cx*16);
                asm volatile("cp.async.cg.shared.global [%0], [%1], 16;"
                             :: "r"(dst), "l"(src));
            }
        }
        asm volatile("cp.async.commit_group;");
        asm volatile("cp.async.wait_group 0;" ::: "memory");
    } else {
#pragma unroll 3
        for (int it = 0; it < 18; it++) {
            int idx = tid + it*256;
            if (idx < NCHUNK) {
                int cx  = idx % 18;
                int row = idx / 18;
                int ry  = row % SH;
                int c   = row / SH;
                int gy  = reflect_idx(y0 + ry - 2, H);
                const float* src = qb + c*HW + gy*W;
                float4 v;
                v.x = src[reflect_idx(x0 - 4 + cx*4,     W)];
                v.y = src[reflect_idx(x0 - 4 + cx*4 + 1, W)];
                v.z = src[reflect_idx(x0 - 4 + cx*4 + 2, W)];
                v.w = src[reflect_idx(x0 - 4 + cx*4 + 3, W)];
                *reinterpret_cast<float4*>(
                    reinterpret_cast<char*>(sq) + row*ROWB + cx*16) = v;
            }
        }
    }
    __syncthreads();

    int xl  = tx * 2;
    int gx0 = x0 + xl;
    int gy  = y0 + ty;

    unsigned long long acc[NC];
#pragma unroll
    for (int cc = 0; cc < NC; cc++) acc[cc] = 0ULL;

    int wbase = b*HW + gy*W + gx0;
#pragma unroll
    for (int dy = 0; dy < 5; dy++) {
        // packed coef pairs: (w[t,gx0], w[t,gx0+1]) — LDG.64, already packed
        unsigned long long C0, C1, C2, C3, C4;
        {
            const float* wp = g_wc + (size_t)(dy*5)*(NB*HW) + wbase;
            C0 = *reinterpret_cast<const unsigned long long*>(wp);
            C1 = *reinterpret_cast<const unsigned long long*>(wp + NB*HW);
            C2 = *reinterpret_cast<const unsigned long long*>(wp + 2*NB*HW);
            C3 = *reinterpret_cast<const unsigned long long*>(wp + 3*NB*HW);
            C4 = *reinterpret_cast<const unsigned long long*>(wp + 4*NB*HW);
        }
        // window q[gx0-2 .. gx0+3] = smem floats [xl+2 .. xl+7] of row (ty+dy)
        const float* rowb = sq + (ty + dy)*SW + xl + 2;
#pragma unroll
        for (int ch = 0; ch < NC; ch++) {
            const float* rp = rowb + ch*(SH*SW);
            float2 a0 = *reinterpret_cast<const float2*>(rp);      // (v0,v1)
            float2 a1 = *reinterpret_cast<const float2*>(rp + 2);  // (v2,v3)
            float2 a2 = *reinterpret_cast<const float2*>(rp + 4);  // (v4,v5)
            unsigned long long A0 = pk2(a0.x, a0.y);
            unsigned long long B0 = pk2(a0.y, a1.x);
            unsigned long long A1 = pk2(a1.x, a1.y);
            unsigned long long B1 = pk2(a1.y, a2.x);
            unsigned long long A2 = pk2(a2.x, a2.y);
            FMA2(acc[ch], C0, A0);
            FMA2(acc[ch], C1, B0);
            FMA2(acc[ch], C2, A1);
            FMA2(acc[ch], C3, B1);
            FMA2(acc[ch], C4, A2);
        }
    }

    // q_out = softmax(unary - F); exp results packed back into acc (reg reuse)
    const float* ub = unary + (size_t)b * NC * HW + gy*W + gx0;
    float s0 = 0.f, s1 = 0.f;
#pragma unroll
    for (int ch = 0; ch < NC; ch++) {
        float2 u = *reinterpret_cast<const float2*>(ub + ch*HW);
        float f0, f1;
        upk2(f0, f1, acc[ch]);
        float e0 = __expf(u.x - f0);
        float e1 = __expf(u.y - f1);
        acc[ch] = pk2(e0, e1);
        s0 += e0; s1 += e1;
    }
    float i0 = 1.f / s0, i1 = 1.f / s1;
    float* qo = qout + (size_t)b * NC * HW + gy*W + gx0;
#pragma unroll
    for (int ch = 0; ch < NC; ch++) {
        float e0, e1;
        upk2(e0, e1, acc[ch]);
        float2 o; o.x = e0*i0; o.y = e1*i1;
        *reinterpret_cast<float2*>(qo + ch*HW) = o;
    }
}

// ---------------------------------------------------------------------------
extern "C" void kernel_launch(void* const* d_in, const int* in_sizes, int n_in,
                              void* d_out, int out_size) {
    const float *unary = nullptr, *image = nullptr, *edges = nullptr;
    for (int i = 0; i < n_in; i++) {
        if      (in_sizes[i] == NB*NC*HW) unary = (const float*)d_in[i];
        else if (in_sizes[i] == NB*3*HW)  image = (const float*)d_in[i];
        else if (in_sizes[i] == NB*HW)    edges = (const float*)d_in[i];
    }
    float* out = (float*)d_out;

    float *qA = nullptr, *qB = nullptr;
    cudaGetSymbolAddress((void**)&qA, g_qA);
    cudaGetSymbolAddress((void**)&qB, g_qB);

    init_softmax<<<(NPIX + 255)/256, 256>>>(unary, qA);
    compute_weights<<<dim3(W/32, H/8, NB), dim3(32, 8)>>>(image, edges);

    dim3 gi(W/TX, H/TY, NB), bi(32, 8);
    const float* cur = qA;
    for (int it = 0; it < 10; it++) {
        float* dst = (it == 9) ? out : ((cur == qA) ? qB : qA);
        crf_iter<<<gi, bi>>>(unary, cur, dst);
        cur = dst;
    }
}